// round 1
// baseline (speedup 1.0000x reference)
#include <cuda_runtime.h>
#include <math.h>

// Problem constants (from reference setup_inputs)
#define B_  256
#define T_  1024
#define I_  3
#define H_  128
#define O_  3

// ---------------------------------------------------------------------------
// Recurrent kernel: one block per batch element, one thread per hidden unit.
// Thread j keeps W_hh row j in registers (128 floats). Hidden state lives in
// shared memory, double-buffered so each timestep costs exactly one barrier.
// Input projection (I=3) is fused: 3 FMAs per thread per step.
// Writes hiddens[b][t][j] to global as it goes.
// ---------------------------------------------------------------------------
__global__ void __launch_bounds__(H_, 2)
rnn_recurrent_kernel(const float* __restrict__ inputs,   // [B, T, I]
                     const float* __restrict__ W_ih,     // [H, I]
                     const float* __restrict__ W_hh,     // [H, H]
                     const float* __restrict__ b_ih,     // [H]
                     const float* __restrict__ b_hh,     // [H]
                     const float* __restrict__ h0,       // [1, H]
                     float* __restrict__ hiddens)        // [B, T, H]
{
    const int b = blockIdx.x;
    const int j = threadIdx.x;

    __shared__ float hbuf[2][H_];   // double-buffered hidden state (16B-aligned rows)

    // Load W_hh row j into registers (fully unrolled -> stays in RF).
    float w[H_];
    const float4* wrow = reinterpret_cast<const float4*>(W_hh + j * H_);
#pragma unroll
    for (int kk = 0; kk < H_ / 4; ++kk) {
        float4 v = wrow[kk];
        w[4 * kk + 0] = v.x;
        w[4 * kk + 1] = v.y;
        w[4 * kk + 2] = v.z;
        w[4 * kk + 3] = v.w;
    }

    const float wi0 = W_ih[j * I_ + 0];
    const float wi1 = W_ih[j * I_ + 1];
    const float wi2 = W_ih[j * I_ + 2];
    const float bias = b_ih[j] + b_hh[j];

    hbuf[0][j] = h0[j];
    __syncthreads();

    const float* inb  = inputs + (size_t)b * T_ * I_;
    float*       hout = hiddens + (size_t)b * T_ * H_;

    int cur = 0;
#pragma unroll 1
    for (int t = 0; t < T_; ++t) {
        // Fused input projection (broadcast loads, L1-cached)
        const float x0 = inb[t * I_ + 0];
        const float x1 = inb[t * I_ + 1];
        const float x2 = inb[t * I_ + 2];
        float acc = fmaf(x0, wi0, fmaf(x1, wi1, fmaf(x2, wi2, bias)));

        // h . W_hh[j,:] — broadcast smem reads, 4 independent FMA chains for ILP
        float a0 = 0.f, a1 = 0.f, a2 = 0.f, a3 = 0.f;
        const float4* h4 = reinterpret_cast<const float4*>(hbuf[cur]);
#pragma unroll
        for (int kk = 0; kk < H_ / 4; ++kk) {
            float4 hv = h4[kk];
            a0 = fmaf(hv.x, w[4 * kk + 0], a0);
            a1 = fmaf(hv.y, w[4 * kk + 1], a1);
            a2 = fmaf(hv.z, w[4 * kk + 2], a2);
            a3 = fmaf(hv.w, w[4 * kk + 3], a3);
        }
        acc += (a0 + a1) + (a2 + a3);

        const float hn = tanhf(acc);
        hbuf[cur ^ 1][j] = hn;       // write other buffer: no WAR on readers
        hout[t * H_ + j] = hn;       // coalesced across j
        cur ^= 1;
        __syncthreads();
    }
}

// ---------------------------------------------------------------------------
// Output projection: out[b][t][o] = hiddens[b][t][:] . W_out[o][:] + b_out[o]
// One warp per (b,t) row; each lane loads 4 h values (float4) -> warp reduce.
// ---------------------------------------------------------------------------
__global__ void rnn_outproj_kernel(const float* __restrict__ hiddens, // [B*T, H]
                                   const float* __restrict__ W_out,   // [O, H]
                                   const float* __restrict__ b_out,   // [O]
                                   float* __restrict__ out)           // [B*T, O]
{
    const int warp = (blockIdx.x * blockDim.x + threadIdx.x) >> 5;
    const int lane = threadIdx.x & 31;
    if (warp >= B_ * T_) return;

    const float4 hv = reinterpret_cast<const float4*>(hiddens + (size_t)warp * H_)[lane];
    const float4 w0 = reinterpret_cast<const float4*>(W_out + 0 * H_)[lane];
    const float4 w1 = reinterpret_cast<const float4*>(W_out + 1 * H_)[lane];
    const float4 w2 = reinterpret_cast<const float4*>(W_out + 2 * H_)[lane];

    float s0 = hv.x * w0.x + hv.y * w0.y + hv.z * w0.z + hv.w * w0.w;
    float s1 = hv.x * w1.x + hv.y * w1.y + hv.z * w1.z + hv.w * w1.w;
    float s2 = hv.x * w2.x + hv.y * w2.y + hv.z * w2.z + hv.w * w2.w;

#pragma unroll
    for (int off = 16; off > 0; off >>= 1) {
        s0 += __shfl_down_sync(0xffffffffu, s0, off);
        s1 += __shfl_down_sync(0xffffffffu, s1, off);
        s2 += __shfl_down_sync(0xffffffffu, s2, off);
    }
    if (lane == 0) {
        float* o = out + (size_t)warp * O_;
        o[0] = s0 + b_out[0];
        o[1] = s1 + b_out[1];
        o[2] = s2 + b_out[2];
    }
}

// ---------------------------------------------------------------------------
// kernel_launch: d_in order per metadata:
//   0: inputs [B,T,I]  1: W_ih [H,I]  2: W_hh [H,H]  3: b_ih [H]
//   4: b_hh [H]        5: h0 [1,H]    6: W_out [O,H] 7: b_out [O]
// d_out: concat(output [B,T,O], hiddens [B,T,H]) as float32.
// ---------------------------------------------------------------------------
extern "C" void kernel_launch(void* const* d_in, const int* in_sizes, int n_in,
                              void* d_out, int out_size)
{
    const float* inputs = (const float*)d_in[0];
    const float* W_ih   = (const float*)d_in[1];
    const float* W_hh   = (const float*)d_in[2];
    const float* b_ih   = (const float*)d_in[3];
    const float* b_hh   = (const float*)d_in[4];
    const float* h0     = (const float*)d_in[5];
    const float* W_out  = (const float*)d_in[6];
    const float* b_out  = (const float*)d_in[7];

    float* out     = (float*)d_out;                       // [B,T,O] first
    float* hiddens = (float*)d_out + (size_t)B_ * T_ * O_; // [B,T,H] second

    rnn_recurrent_kernel<<<B_, H_>>>(inputs, W_ih, W_hh, b_ih, b_hh, h0, hiddens);

    // one warp per (b,t) row: 8 warps per 256-thread block
    const int rows = B_ * T_;
    const int warps_per_block = 256 / 32;
    const int blocks = (rows + warps_per_block - 1) / warps_per_block;
    rnn_outproj_kernel<<<blocks, 256>>>(hiddens, W_out, b_out, out);
}